// round 5
// baseline (speedup 1.0000x reference)
#include <cuda_runtime.h>
#include <math.h>

#define N_NODES 50000
#define N_EDGES 1600000
#define E_TOT   (N_EDGES + N_NODES)
#define HID     128
#define IND     13
#define OUTD    5
#define SCAN_BS 512
#define NBLK    ((N_NODES + SCAN_BS - 1) / SCAN_BS)   // 98

// ---------------- scratch (static device globals; no allocation) ----------------
__device__ int    g_src[E_TOT];
__device__ int    g_dst[E_TOT];
__device__ int    g_ssrc[E_TOT];           // CSR-sorted source indices (by dst)
__device__ int    g_cnt[N_NODES];
__device__ int    g_off[N_NODES + 1];
__device__ int    g_cur[N_NODES];
__device__ int    g_bsum[NBLK + 1];
__device__ float4 g_h[N_NODES * 32];       // transformed features [N][128] as float4
__device__ float4 g_feat[N_NODES * 32];    // layer input/output [N][128] as float4
__device__ float  g_as[N_NODES];
__device__ float  g_ad[N_NODES];
__device__ float  g_h5[N_NODES * OUTD];

// ---------------- CSR build ----------------
__global__ void k_zero_cnt() {
    int i = blockIdx.x * blockDim.x + threadIdx.x;
    if (i < N_NODES) g_cnt[i] = 0;
}

__global__ void k_hist(const int* __restrict__ ei) {
    int e = blockIdx.x * blockDim.x + threadIdx.x;
    if (e >= E_TOT) return;
    int s, d;
    if (e < N_EDGES) { s = ei[e]; d = ei[N_EDGES + e]; }   // int32 (JAX x64 disabled)
    else             { s = d = e - N_EDGES; }              // self loops
    g_src[e] = s; g_dst[e] = d;
    atomicAdd(&g_cnt[d], 1);
}

__global__ void k_blocksum() {
    __shared__ int sm[SCAN_BS];
    int i = blockIdx.x * SCAN_BS + threadIdx.x;
    sm[threadIdx.x] = (i < N_NODES) ? g_cnt[i] : 0;
    __syncthreads();
    for (int o = SCAN_BS / 2; o > 0; o >>= 1) {
        if (threadIdx.x < o) sm[threadIdx.x] += sm[threadIdx.x + o];
        __syncthreads();
    }
    if (threadIdx.x == 0) g_bsum[blockIdx.x] = sm[0];
}

__global__ void k_scantop() {
    if (threadIdx.x == 0 && blockIdx.x == 0) {
        int acc = 0;
        for (int b = 0; b < NBLK; ++b) { int v = g_bsum[b]; g_bsum[b] = acc; acc += v; }
        g_off[N_NODES] = acc;   // == E_TOT
    }
}

__global__ void k_offsets() {
    __shared__ int sm[SCAN_BS];
    int i = blockIdx.x * SCAN_BS + threadIdx.x;
    int v = (i < N_NODES) ? g_cnt[i] : 0;
    sm[threadIdx.x] = v;
    __syncthreads();
    for (int o = 1; o < SCAN_BS; o <<= 1) {          // Hillis-Steele inclusive
        int t = (threadIdx.x >= o) ? sm[threadIdx.x - o] : 0;
        __syncthreads();
        sm[threadIdx.x] += t;
        __syncthreads();
    }
    if (i < N_NODES) {
        int excl = sm[threadIdx.x] - v + g_bsum[blockIdx.x];
        g_off[i] = excl;
        g_cur[i] = excl;
    }
}

__global__ void k_fill() {
    int e = blockIdx.x * blockDim.x + threadIdx.x;
    if (e >= E_TOT) return;
    int d = g_dst[e];
    int pos = atomicAdd(&g_cur[d], 1);
    g_ssrc[pos] = g_src[e];
}

// ---------------- layer 1 GEMM (K=13) + fused attention dots ----------------
__global__ void k_gemm1(const float* __restrict__ x, const float* __restrict__ W1,
                        const float* __restrict__ a_src, const float* __restrict__ a_dst) {
    __shared__ __align__(16) float Ws[IND * HID];
    __shared__ __align__(16) float As[HID];
    __shared__ __align__(16) float Ad[HID];
    for (int i = threadIdx.x; i < IND * HID; i += blockDim.x) Ws[i] = W1[i];
    for (int i = threadIdx.x; i < HID; i += blockDim.x) { As[i] = a_src[i]; Ad[i] = a_dst[i]; }
    __syncthreads();
    int warp = threadIdx.x >> 5, lane = threadIdx.x & 31;
    int node = blockIdx.x * 8 + warp;
    if (node >= N_NODES) return;
    float xv[IND];
#pragma unroll
    for (int k = 0; k < IND; ++k) xv[k] = x[node * IND + k];
    float4 acc = {0.f, 0.f, 0.f, 0.f};
#pragma unroll
    for (int k = 0; k < IND; ++k) {
        float4 w = *(const float4*)&Ws[k * HID + lane * 4];
        acc.x += xv[k] * w.x; acc.y += xv[k] * w.y;
        acc.z += xv[k] * w.z; acc.w += xv[k] * w.w;
    }
    g_h[node * 32 + lane] = acc;
    float4 a1 = *(const float4*)&As[lane * 4];
    float4 a2 = *(const float4*)&Ad[lane * 4];
    float s1 = acc.x * a1.x + acc.y * a1.y + acc.z * a1.z + acc.w * a1.w;
    float s2 = acc.x * a2.x + acc.y * a2.y + acc.z * a2.z + acc.w * a2.w;
#pragma unroll
    for (int o = 16; o; o >>= 1) {
        s1 += __shfl_xor_sync(0xffffffffu, s1, o);
        s2 += __shfl_xor_sync(0xffffffffu, s2, o);
    }
    if (lane == 0) { g_as[node] = s1; g_ad[node] = s2; }
}

// ---------------- layer 2 GEMM (128x128, fp32, smem tiled) ----------------
// grid: ((N+31)/32, 2), block 256. Each warp owns 4 rows x 64 cols; lane owns 2 cols.
__global__ void k_gemm2(const float* __restrict__ W) {
    __shared__ __align__(16) float Ws[HID * 64];      // [k][64-col block]  (32 KB)
    __shared__ float Fs[32][33];
    int colBase = blockIdx.y * 64;
    for (int i = threadIdx.x; i < HID * 64; i += 256)
        Ws[i] = W[(i >> 6) * HID + colBase + (i & 63)];
    int warp = threadIdx.x >> 5, lane = threadIdx.x & 31;
    int rowBase = blockIdx.x * 32;
    const float* feat = (const float*)g_feat;
    float acc[4][2];
#pragma unroll
    for (int r = 0; r < 4; ++r) { acc[r][0] = 0.f; acc[r][1] = 0.f; }
    for (int kc = 0; kc < HID; kc += 32) {
        __syncthreads();
        for (int i = threadIdx.x; i < 32 * 32; i += 256) {
            int r = i >> 5, k = i & 31;
            int gr = rowBase + r;
            Fs[r][k] = (gr < N_NODES) ? feat[gr * HID + kc + k] : 0.f;
        }
        __syncthreads();
#pragma unroll 8
        for (int k = 0; k < 32; ++k) {
            float2 w = *(const float2*)&Ws[(kc + k) * 64 + lane * 2];
#pragma unroll
            for (int r = 0; r < 4; ++r) {
                float f = Fs[warp * 4 + r][k];
                acc[r][0] += f * w.x;
                acc[r][1] += f * w.y;
            }
        }
    }
    float* hout = (float*)g_h;
#pragma unroll
    for (int r = 0; r < 4; ++r) {
        int gr = rowBase + warp * 4 + r;
        if (gr < N_NODES) {
            float2 o = make_float2(acc[r][0], acc[r][1]);
            *(float2*)&hout[gr * HID + colBase + lane * 2] = o;
        }
    }
}

// attention dots for layer 2 (h row . a_src / a_dst)
__global__ void k_rowdot(const float* __restrict__ a_src, const float* __restrict__ a_dst) {
    int warp = threadIdx.x >> 5, lane = threadIdx.x & 31;
    int node = blockIdx.x * 8 + warp;
    if (node >= N_NODES) return;
    float4 hv = g_h[node * 32 + lane];
    float4 a1 = make_float4(a_src[lane * 4], a_src[lane * 4 + 1], a_src[lane * 4 + 2], a_src[lane * 4 + 3]);
    float4 a2 = make_float4(a_dst[lane * 4], a_dst[lane * 4 + 1], a_dst[lane * 4 + 2], a_dst[lane * 4 + 3]);
    float s1 = hv.x * a1.x + hv.y * a1.y + hv.z * a1.z + hv.w * a1.w;
    float s2 = hv.x * a2.x + hv.y * a2.y + hv.z * a2.z + hv.w * a2.w;
#pragma unroll
    for (int o = 16; o; o >>= 1) {
        s1 += __shfl_xor_sync(0xffffffffu, s1, o);
        s2 += __shfl_xor_sync(0xffffffffu, s2, o);
    }
    if (lane == 0) { g_as[node] = s1; g_ad[node] = s2; }
}

// ---------------- fused softmax-aggregation, F=128 (warp per node) ----------------
__global__ void k_agg128(const float* __restrict__ b, int relu) {
    int warp = threadIdx.x >> 5, lane = threadIdx.x & 31;
    int i = blockIdx.x * 8 + warp;
    if (i >= N_NODES) return;
    int start = g_off[i], end = g_off[i + 1];
    float adi = g_ad[i];
    // pass 1: per-target max (lanes parallel over edges)
    float m = -1e30f;
    for (int j = start + lane; j < end; j += 32) {
        float e = g_as[g_ssrc[j]] + adi;
        e = e > 0.f ? e : 0.2f * e;
        m = fmaxf(m, e);
    }
#pragma unroll
    for (int o = 16; o; o >>= 1) m = fmaxf(m, __shfl_xor_sync(0xffffffffu, m, o));
    // pass 2: warp-cooperative weighted gather (no atomics)
    float4 acc = {0.f, 0.f, 0.f, 0.f};
    float denom = 0.f;
    for (int j = start; j < end; ++j) {
        int s = g_ssrc[j];                       // broadcast load
        float e = g_as[s] + adi;                 // broadcast load
        e = e > 0.f ? e : 0.2f * e;
        float ex = __expf(e - m);
        denom += ex;
        float4 hv = g_h[s * 32 + lane];          // coalesced 512B gather
        acc.x += ex * hv.x; acc.y += ex * hv.y;
        acc.z += ex * hv.z; acc.w += ex * hv.w;
    }
    float inv = 1.f / (denom + 1e-16f);
    float4 bv = make_float4(b[lane * 4], b[lane * 4 + 1], b[lane * 4 + 2], b[lane * 4 + 3]);
    float4 r;
    r.x = acc.x * inv + bv.x; r.y = acc.y * inv + bv.y;
    r.z = acc.z * inv + bv.z; r.w = acc.w * inv + bv.w;
    if (relu) {
        r.x = fmaxf(r.x, 0.f); r.y = fmaxf(r.y, 0.f);
        r.z = fmaxf(r.z, 0.f); r.w = fmaxf(r.w, 0.f);
    }
    g_feat[i * 32 + lane] = r;
}

// ---------------- layer 3 GEMM (K=128 -> 5) + fused attention dots ----------------
__global__ void k_gemm3(const float* __restrict__ W3,
                        const float* __restrict__ a_src, const float* __restrict__ a_dst) {
    __shared__ float Ws[HID * OUTD];
    __shared__ float As[OUTD], Ad[OUTD];
    for (int i = threadIdx.x; i < HID * OUTD; i += blockDim.x) Ws[i] = W3[i];
    if (threadIdx.x < OUTD) { As[threadIdx.x] = a_src[threadIdx.x]; Ad[threadIdx.x] = a_dst[threadIdx.x]; }
    __syncthreads();
    int warp = threadIdx.x >> 5, lane = threadIdx.x & 31;
    int node = blockIdx.x * 8 + warp;
    if (node >= N_NODES) return;
    float4 f = g_feat[node * 32 + lane];
    int k0 = lane * 4;
    float hc[OUTD];
#pragma unroll
    for (int c = 0; c < OUTD; ++c) {
        float s = f.x * Ws[(k0 + 0) * OUTD + c] + f.y * Ws[(k0 + 1) * OUTD + c]
                + f.z * Ws[(k0 + 2) * OUTD + c] + f.w * Ws[(k0 + 3) * OUTD + c];
#pragma unroll
        for (int o = 16; o; o >>= 1) s += __shfl_xor_sync(0xffffffffu, s, o);
        hc[c] = s;
    }
    if (lane == 0) {
        float s1 = 0.f, s2 = 0.f;
#pragma unroll
        for (int c = 0; c < OUTD; ++c) {
            g_h5[node * OUTD + c] = hc[c];
            s1 += hc[c] * As[c];
            s2 += hc[c] * Ad[c];
        }
        g_as[node] = s1; g_ad[node] = s2;
    }
}

// ---------------- fused aggregation F=5 + bias + log_softmax (thread per node) ----------------
__global__ void k_agg5(const float* __restrict__ b3, float* __restrict__ out) {
    int i = blockIdx.x * blockDim.x + threadIdx.x;
    if (i >= N_NODES) return;
    int start = g_off[i], end = g_off[i + 1];
    float adi = g_ad[i];
    float m = -1e30f;
    for (int j = start; j < end; ++j) {
        float e = g_as[g_ssrc[j]] + adi;
        e = e > 0.f ? e : 0.2f * e;
        m = fmaxf(m, e);
    }
    float acc[OUTD] = {0.f, 0.f, 0.f, 0.f, 0.f};
    float denom = 0.f;
    for (int j = start; j < end; ++j) {
        int s = g_ssrc[j];
        float e = g_as[s] + adi;
        e = e > 0.f ? e : 0.2f * e;
        float ex = __expf(e - m);
        denom += ex;
#pragma unroll
        for (int c = 0; c < OUTD; ++c) acc[c] += ex * g_h5[s * OUTD + c];
    }
    float inv = 1.f / (denom + 1e-16f);
    float v[OUTD];
    float mx = -1e30f;
#pragma unroll
    for (int c = 0; c < OUTD; ++c) { v[c] = acc[c] * inv + b3[c]; mx = fmaxf(mx, v[c]); }
    float se = 0.f;
#pragma unroll
    for (int c = 0; c < OUTD; ++c) se += __expf(v[c] - mx);
    float lse = mx + logf(se);
#pragma unroll
    for (int c = 0; c < OUTD; ++c) out[i * OUTD + c] = v[c] - lse;
}

// ---------------- launch ----------------
extern "C" void kernel_launch(void* const* d_in, const int* in_sizes, int n_in,
                              void* d_out, int out_size) {
    const float* x   = (const float*)d_in[0];
    const int*   ei  = (const int*)d_in[1];       // int32: JAX x64 is disabled
    const float* W1  = (const float*)d_in[2];
    const float* as1 = (const float*)d_in[3];
    const float* ad1 = (const float*)d_in[4];
    const float* b1  = (const float*)d_in[5];
    const float* W2  = (const float*)d_in[6];
    const float* as2 = (const float*)d_in[7];
    const float* ad2 = (const float*)d_in[8];
    const float* b2  = (const float*)d_in[9];
    const float* W3  = (const float*)d_in[10];
    const float* as3 = (const float*)d_in[11];
    const float* ad3 = (const float*)d_in[12];
    const float* b3  = (const float*)d_in[13];
    float* out = (float*)d_out;

    // CSR build (shared by all 3 layers; rebuilt every call — no caching)
    k_zero_cnt<<<(N_NODES + 255) / 256, 256>>>();
    k_hist<<<(E_TOT + 255) / 256, 256>>>(ei);
    k_blocksum<<<NBLK, SCAN_BS>>>();
    k_scantop<<<1, 32>>>();
    k_offsets<<<NBLK, SCAN_BS>>>();
    k_fill<<<(E_TOT + 255) / 256, 256>>>();

    int nwb = (N_NODES + 7) / 8;   // warp-per-node grids

    // layer 1
    k_gemm1<<<nwb, 256>>>(x, W1, as1, ad1);
    k_agg128<<<nwb, 256>>>(b1, 1);
    // layer 2
    {
        dim3 g((N_NODES + 31) / 32, 2);
        k_gemm2<<<g, 256>>>(W2);
    }
    k_rowdot<<<nwb, 256>>>(as2, ad2);
    k_agg128<<<nwb, 256>>>(b2, 1);
    // layer 3
    k_gemm3<<<nwb, 256>>>(W3, as3, ad3);
    k_agg5<<<(N_NODES + 255) / 256, 256>>>(b3, out);
}

// round 6
// speedup vs baseline: 1.1904x; 1.1904x over previous
#include <cuda_runtime.h>
#include <cuda_fp16.h>
#include <math.h>

#define N_NODES 50000
#define N_EDGES 1600000
#define E_TOT   (N_EDGES + N_NODES)
#define HID     128
#define IND     13
#define OUTD    5
#define SCAN_BS 512
#define NBLK    ((N_NODES + SCAN_BS - 1) / SCAN_BS)   // 98

// ---------------- scratch (static device globals; no allocation) ----------------
__device__ int    g_ssrc[E_TOT];           // CSR-sorted source indices (by dst)
__device__ int    g_cnt[N_NODES];
__device__ int    g_off[N_NODES + 1];
__device__ int    g_cur[N_NODES];
__device__ int    g_bsum[NBLK + 1];
__device__ __align__(8) __half g_hh[N_NODES * HID];  // transformed features, fp16
__device__ float4 g_feat[N_NODES * 32];    // layer input/output [N][128] as float4
__device__ float  g_as[N_NODES];
__device__ float  g_ad[N_NODES];
__device__ float  g_h5[N_NODES * OUTD];

// ---------------- CSR build ----------------
__global__ void k_zero_cnt() {
    int i = blockIdx.x * blockDim.x + threadIdx.x;
    if (i < N_NODES) g_cnt[i] = 0;
}

__global__ void k_hist(const int* __restrict__ ei) {
    int e = blockIdx.x * blockDim.x + threadIdx.x;
    if (e >= E_TOT) return;
    int d = (e < N_EDGES) ? ei[N_EDGES + e] : e - N_EDGES;   // int32 (JAX x64 disabled)
    atomicAdd(&g_cnt[d], 1);
}

__global__ void k_blocksum() {
    __shared__ int sm[SCAN_BS];
    int i = blockIdx.x * SCAN_BS + threadIdx.x;
    sm[threadIdx.x] = (i < N_NODES) ? g_cnt[i] : 0;
    __syncthreads();
    for (int o = SCAN_BS / 2; o > 0; o >>= 1) {
        if (threadIdx.x < o) sm[threadIdx.x] += sm[threadIdx.x + o];
        __syncthreads();
    }
    if (threadIdx.x == 0) g_bsum[blockIdx.x] = sm[0];
}

__global__ void k_scantop() {          // parallel scan over NBLK(=98) block sums
    __shared__ int sm[128];
    int t = threadIdx.x;
    int v = (t < NBLK) ? g_bsum[t] : 0;
    sm[t] = v;
    __syncthreads();
    for (int o = 1; o < 128; o <<= 1) {
        int u = (t >= o) ? sm[t - o] : 0;
        __syncthreads();
        sm[t] += u;
        __syncthreads();
    }
    if (t < NBLK) g_bsum[t] = sm[t] - v;      // exclusive
    if (t == 127) g_off[N_NODES] = sm[127];   // == E_TOT
}

__global__ void k_offsets() {
    __shared__ int sm[SCAN_BS];
    int i = blockIdx.x * SCAN_BS + threadIdx.x;
    int v = (i < N_NODES) ? g_cnt[i] : 0;
    sm[threadIdx.x] = v;
    __syncthreads();
    for (int o = 1; o < SCAN_BS; o <<= 1) {          // Hillis-Steele inclusive
        int t = (threadIdx.x >= o) ? sm[threadIdx.x - o] : 0;
        __syncthreads();
        sm[threadIdx.x] += t;
        __syncthreads();
    }
    if (i < N_NODES) {
        int excl = sm[threadIdx.x] - v + g_bsum[blockIdx.x];
        g_off[i] = excl;
        g_cur[i] = excl;
    }
}

__global__ void k_fill(const int* __restrict__ ei) {
    int e = blockIdx.x * blockDim.x + threadIdx.x;
    if (e >= E_TOT) return;
    int s, d;
    if (e < N_EDGES) { s = ei[e]; d = ei[N_EDGES + e]; }
    else             { s = d = e - N_EDGES; }
    int pos = atomicAdd(&g_cur[d], 1);
    g_ssrc[pos] = s;
}

// ---------------- helpers ----------------
__device__ __forceinline__ uint2 pack_half4(float a, float b, float c, float d) {
    __half2 h0 = __float22half2_rn(make_float2(a, b));
    __half2 h1 = __float22half2_rn(make_float2(c, d));
    uint2 u;
    u.x = *reinterpret_cast<unsigned*>(&h0);
    u.y = *reinterpret_cast<unsigned*>(&h1);
    return u;
}
__device__ __forceinline__ float4 unpack_half4(uint2 u) {
    __half2 h0 = *reinterpret_cast<__half2*>(&u.x);
    __half2 h1 = *reinterpret_cast<__half2*>(&u.y);
    float2 f0 = __half22float2(h0), f1 = __half22float2(h1);
    return make_float4(f0.x, f0.y, f1.x, f1.y);
}

// ---------------- layer 1 GEMM (K=13) + fused attention dots ----------------
__global__ void k_gemm1(const float* __restrict__ x, const float* __restrict__ W1,
                        const float* __restrict__ a_src, const float* __restrict__ a_dst) {
    __shared__ __align__(16) float Ws[IND * HID];
    __shared__ __align__(16) float As[HID];
    __shared__ __align__(16) float Ad[HID];
    for (int i = threadIdx.x; i < IND * HID; i += blockDim.x) Ws[i] = W1[i];
    for (int i = threadIdx.x; i < HID; i += blockDim.x) { As[i] = a_src[i]; Ad[i] = a_dst[i]; }
    __syncthreads();
    int warp = threadIdx.x >> 5, lane = threadIdx.x & 31;
    int node = blockIdx.x * 8 + warp;
    if (node >= N_NODES) return;
    float xv[IND];
#pragma unroll
    for (int k = 0; k < IND; ++k) xv[k] = x[node * IND + k];
    float4 acc = {0.f, 0.f, 0.f, 0.f};
#pragma unroll
    for (int k = 0; k < IND; ++k) {
        float4 w = *(const float4*)&Ws[k * HID + lane * 4];
        acc.x += xv[k] * w.x; acc.y += xv[k] * w.y;
        acc.z += xv[k] * w.z; acc.w += xv[k] * w.w;
    }
    ((uint2*)g_hh)[node * 32 + lane] = pack_half4(acc.x, acc.y, acc.z, acc.w);
    float4 a1 = *(const float4*)&As[lane * 4];
    float4 a2 = *(const float4*)&Ad[lane * 4];
    float s1 = acc.x * a1.x + acc.y * a1.y + acc.z * a1.z + acc.w * a1.w;
    float s2 = acc.x * a2.x + acc.y * a2.y + acc.z * a2.z + acc.w * a2.w;
#pragma unroll
    for (int o = 16; o; o >>= 1) {
        s1 += __shfl_xor_sync(0xffffffffu, s1, o);
        s2 += __shfl_xor_sync(0xffffffffu, s2, o);
    }
    if (lane == 0) { g_as[node] = s1; g_ad[node] = s2; }
}

// ---------------- layer 2 GEMM: 64x64 tile, 4x4 per thread, fp32, half output ----
// grid ((N+63)/64, 2), block 256 (16x16 threads).
__global__ void k_gemm2(const float* __restrict__ W) {
    __shared__ float As[32][68];   // [k][row] (transposed feat tile), pad 68 (16B-aligned rows)
    __shared__ float Bs[32][64];   // [k][col]
    int rowBase = blockIdx.x * 64;
    int colBase = blockIdx.y * 64;
    int tx = threadIdx.x & 15, ty = threadIdx.x >> 4;
    const float* feat = (const float*)g_feat;
    float acc[4][4];
#pragma unroll
    for (int i = 0; i < 4; ++i)
#pragma unroll
        for (int j = 0; j < 4; ++j) acc[i][j] = 0.f;

    for (int kc = 0; kc < HID; kc += 32) {
        __syncthreads();
        // load feat tile transposed: As[k][r] = feat[rowBase+r][kc+k]
#pragma unroll
        for (int v = threadIdx.x * 4; v < 64 * 32; v += 256 * 4) {
            int r = v >> 5, k = v & 31;
            int gr = rowBase + r;
            float4 f = (gr < N_NODES) ? *(const float4*)&feat[gr * HID + kc + k]
                                      : make_float4(0.f, 0.f, 0.f, 0.f);
            As[k + 0][r] = f.x; As[k + 1][r] = f.y;
            As[k + 2][r] = f.z; As[k + 3][r] = f.w;
        }
        // load W tile: Bs[k][c] = W[(kc+k)*128 + colBase+c]
#pragma unroll
        for (int v = threadIdx.x * 4; v < 32 * 64; v += 256 * 4) {
            int k = v >> 6, c = v & 63;
            *(float4*)&Bs[k][c] = *(const float4*)&W[(kc + k) * HID + colBase + c];
        }
        __syncthreads();
#pragma unroll
        for (int k = 0; k < 32; ++k) {
            float4 a = *(const float4*)&As[k][ty * 4];
            float4 b = *(const float4*)&Bs[k][tx * 4];
            float av[4] = {a.x, a.y, a.z, a.w};
            float bv[4] = {b.x, b.y, b.z, b.w};
#pragma unroll
            for (int i = 0; i < 4; ++i)
#pragma unroll
                for (int j = 0; j < 4; ++j) acc[i][j] += av[i] * bv[j];
        }
    }
    // epilogue: write half4 per row (cols colBase+tx*4 .. +3)
#pragma unroll
    for (int i = 0; i < 4; ++i) {
        int gr = rowBase + ty * 4 + i;
        if (gr < N_NODES) {
            ((uint2*)g_hh)[gr * 32 + (colBase >> 2) + tx] =
                pack_half4(acc[i][0], acc[i][1], acc[i][2], acc[i][3]);
        }
    }
}

// attention dots for layer 2 (h row . a_src / a_dst), h in fp16
__global__ void k_rowdot(const float* __restrict__ a_src, const float* __restrict__ a_dst) {
    int warp = threadIdx.x >> 5, lane = threadIdx.x & 31;
    int node = blockIdx.x * 8 + warp;
    if (node >= N_NODES) return;
    float4 hv = unpack_half4(((const uint2*)g_hh)[node * 32 + lane]);
    float4 a1 = make_float4(a_src[lane * 4], a_src[lane * 4 + 1], a_src[lane * 4 + 2], a_src[lane * 4 + 3]);
    float4 a2 = make_float4(a_dst[lane * 4], a_dst[lane * 4 + 1], a_dst[lane * 4 + 2], a_dst[lane * 4 + 3]);
    float s1 = hv.x * a1.x + hv.y * a1.y + hv.z * a1.z + hv.w * a1.w;
    float s2 = hv.x * a2.x + hv.y * a2.y + hv.z * a2.z + hv.w * a2.w;
#pragma unroll
    for (int o = 16; o; o >>= 1) {
        s1 += __shfl_xor_sync(0xffffffffu, s1, o);
        s2 += __shfl_xor_sync(0xffffffffu, s2, o);
    }
    if (lane == 0) { g_as[node] = s1; g_ad[node] = s2; }
}

// ---------------- fused softmax-aggregation, F=128 (warp per node, fp16 gather) ----
__global__ void k_agg128(const float* __restrict__ b, int relu) {
    int warp = threadIdx.x >> 5, lane = threadIdx.x & 31;
    int i = blockIdx.x * 8 + warp;
    if (i >= N_NODES) return;
    int start = g_off[i], end = g_off[i + 1];
    float adi = g_ad[i];
    // pass 1: per-target max (lanes parallel over edges)
    float m = -1e30f;
    for (int j = start + lane; j < end; j += 32) {
        float e = g_as[g_ssrc[j]] + adi;
        e = e > 0.f ? e : 0.2f * e;
        m = fmaxf(m, e);
    }
#pragma unroll
    for (int o = 16; o; o >>= 1) m = fmaxf(m, __shfl_xor_sync(0xffffffffu, m, o));
    // pass 2: warp-cooperative weighted gather (no atomics), 256B/edge fp16
    float4 acc = {0.f, 0.f, 0.f, 0.f};
    float denom = 0.f;
    const uint2* hh = (const uint2*)g_hh;
    for (int j = start; j < end; ++j) {
        int s = g_ssrc[j];                       // broadcast load
        float e = g_as[s] + adi;                 // broadcast load
        e = e > 0.f ? e : 0.2f * e;
        float ex = __expf(e - m);
        denom += ex;
        float4 hv = unpack_half4(hh[s * 32 + lane]);   // coalesced 256B gather
        acc.x += ex * hv.x; acc.y += ex * hv.y;
        acc.z += ex * hv.z; acc.w += ex * hv.w;
    }
    float inv = 1.f / (denom + 1e-16f);
    float4 bv = make_float4(b[lane * 4], b[lane * 4 + 1], b[lane * 4 + 2], b[lane * 4 + 3]);
    float4 r;
    r.x = acc.x * inv + bv.x; r.y = acc.y * inv + bv.y;
    r.z = acc.z * inv + bv.z; r.w = acc.w * inv + bv.w;
    if (relu) {
        r.x = fmaxf(r.x, 0.f); r.y = fmaxf(r.y, 0.f);
        r.z = fmaxf(r.z, 0.f); r.w = fmaxf(r.w, 0.f);
    }
    g_feat[i * 32 + lane] = r;
}

// ---------------- layer 3 GEMM (K=128 -> 5) + fused attention dots ----------------
__global__ void k_gemm3(const float* __restrict__ W3,
                        const float* __restrict__ a_src, const float* __restrict__ a_dst) {
    __shared__ float Ws[HID * OUTD];
    __shared__ float As[OUTD], Ad[OUTD];
    for (int i = threadIdx.x; i < HID * OUTD; i += blockDim.x) Ws[i] = W3[i];
    if (threadIdx.x < OUTD) { As[threadIdx.x] = a_src[threadIdx.x]; Ad[threadIdx.x] = a_dst[threadIdx.x]; }
    __syncthreads();
    int warp = threadIdx.x >> 5, lane = threadIdx.x & 31;
    int node = blockIdx.x * 8 + warp;
    if (node >= N_NODES) return;
    float4 f = g_feat[node * 32 + lane];
    int k0 = lane * 4;
    float hc[OUTD];
#pragma unroll
    for (int c = 0; c < OUTD; ++c) {
        float s = f.x * Ws[(k0 + 0) * OUTD + c] + f.y * Ws[(k0 + 1) * OUTD + c]
                + f.z * Ws[(k0 + 2) * OUTD + c] + f.w * Ws[(k0 + 3) * OUTD + c];
#pragma unroll
        for (int o = 16; o; o >>= 1) s += __shfl_xor_sync(0xffffffffu, s, o);
        hc[c] = s;
    }
    if (lane == 0) {
        float s1 = 0.f, s2 = 0.f;
#pragma unroll
        for (int c = 0; c < OUTD; ++c) {
            g_h5[node * OUTD + c] = hc[c];
            s1 += hc[c] * As[c];
            s2 += hc[c] * Ad[c];
        }
        g_as[node] = s1; g_ad[node] = s2;
    }
}

// ---------------- fused aggregation F=5 + bias + log_softmax (warp per node) -------
__global__ void k_agg5(const float* __restrict__ b3, float* __restrict__ out) {
    int warp = threadIdx.x >> 5, lane = threadIdx.x & 31;
    int i = blockIdx.x * 8 + warp;
    if (i >= N_NODES) return;
    int start = g_off[i], end = g_off[i + 1];
    float adi = g_ad[i];
    float m = -1e30f;
    for (int j = start + lane; j < end; j += 32) {
        float e = g_as[g_ssrc[j]] + adi;
        e = e > 0.f ? e : 0.2f * e;
        m = fmaxf(m, e);
    }
#pragma unroll
    for (int o = 16; o; o >>= 1) m = fmaxf(m, __shfl_xor_sync(0xffffffffu, m, o));
    float a0 = 0.f, a1 = 0.f, a2 = 0.f, a3 = 0.f, a4 = 0.f, denom = 0.f;
    for (int j = start + lane; j < end; j += 32) {
        int s = g_ssrc[j];
        float e = g_as[s] + adi;
        e = e > 0.f ? e : 0.2f * e;
        float ex = __expf(e - m);
        denom += ex;
        const float* hp = &g_h5[s * OUTD];
        a0 += ex * hp[0]; a1 += ex * hp[1]; a2 += ex * hp[2];
        a3 += ex * hp[3]; a4 += ex * hp[4];
    }
#pragma unroll
    for (int o = 16; o; o >>= 1) {
        denom += __shfl_xor_sync(0xffffffffu, denom, o);
        a0 += __shfl_xor_sync(0xffffffffu, a0, o);
        a1 += __shfl_xor_sync(0xffffffffu, a1, o);
        a2 += __shfl_xor_sync(0xffffffffu, a2, o);
        a3 += __shfl_xor_sync(0xffffffffu, a3, o);
        a4 += __shfl_xor_sync(0xffffffffu, a4, o);
    }
    if (lane == 0) {
        float inv = 1.f / (denom + 1e-16f);
        float v[OUTD] = {a0 * inv + b3[0], a1 * inv + b3[1], a2 * inv + b3[2],
                         a3 * inv + b3[3], a4 * inv + b3[4]};
        float mx = -1e30f;
#pragma unroll
        for (int c = 0; c < OUTD; ++c) mx = fmaxf(mx, v[c]);
        float se = 0.f;
#pragma unroll
        for (int c = 0; c < OUTD; ++c) se += __expf(v[c] - mx);
        float lse = mx + logf(se);
#pragma unroll
        for (int c = 0; c < OUTD; ++c) out[i * OUTD + c] = v[c] - lse;
    }
}

// ---------------- launch ----------------
extern "C" void kernel_launch(void* const* d_in, const int* in_sizes, int n_in,
                              void* d_out, int out_size) {
    const float* x   = (const float*)d_in[0];
    const int*   ei  = (const int*)d_in[1];       // int32: JAX x64 is disabled
    const float* W1  = (const float*)d_in[2];
    const float* as1 = (const float*)d_in[3];
    const float* ad1 = (const float*)d_in[4];
    const float* b1  = (const float*)d_in[5];
    const float* W2  = (const float*)d_in[6];
    const float* as2 = (const float*)d_in[7];
    const float* ad2 = (const float*)d_in[8];
    const float* b2  = (const float*)d_in[9];
    const float* W3  = (const float*)d_in[10];
    const float* as3 = (const float*)d_in[11];
    const float* ad3 = (const float*)d_in[12];
    const float* b3  = (const float*)d_in[13];
    float* out = (float*)d_out;

    // CSR build (shared by all 3 layers; rebuilt every call — no caching)
    k_zero_cnt<<<(N_NODES + 255) / 256, 256>>>();
    k_hist<<<(E_TOT + 255) / 256, 256>>>(ei);
    k_blocksum<<<NBLK, SCAN_BS>>>();
    k_scantop<<<1, 128>>>();
    k_offsets<<<NBLK, SCAN_BS>>>();
    k_fill<<<(E_TOT + 255) / 256, 256>>>(ei);

    int nwb = (N_NODES + 7) / 8;   // warp-per-node grids

    // layer 1
    k_gemm1<<<nwb, 256>>>(x, W1, as1, ad1);
    k_agg128<<<nwb, 256>>>(b1, 1);
    // layer 2
    {
        dim3 g((N_NODES + 63) / 64, 2);
        k_gemm2<<<g, 256>>>(W2);
    }
    k_rowdot<<<nwb, 256>>>(as2, ad2);
    k_agg128<<<nwb, 256>>>(b2, 1);
    // layer 3
    k_gemm3<<<nwb, 256>>>(W3, as3, ad3);
    k_agg5<<<nwb, 256>>>(b3, out);
}